// round 14
// baseline (speedup 1.0000x reference)
#include <cuda_runtime.h>
#include <cuda_fp16.h>
#include <cuda_bf16.h>
#include <mma.h>
#include <cstdint>

using namespace nvcuda;

#define NN    50000
#define EMAX  1700000
#define HEADS 8

// Scratch (no cudaMalloc allowed)
__device__ __half g_KV[NN * 256];          // per node: 128 K halves | 128 V halves
__device__ __half g_Q[NN * 128];
__device__ int    g_count[NN];             // zero at load; re-zeroed every call
__device__ int    g_rowstart[NN + 1];
__device__ int    g_cursor[NN];
__device__ unsigned long long g_scanstate[256];
__device__ int    g_sorted_src[EMAX];

#define SCAN_BLOCKS 196   // 196*256 = 50176 >= NN
#define GEMM_SMEM   52224 // 17408 (A) + 34816 (B / tail C-staging)

// ---------------------------------------------------------------------------
// Fused K/Q/V projection via WMMA. One block: 64 rows x full 128 cols,
// all 3 matrices. 8 warps in 2x4, each a 32x32 tile (2x2 fragments).
// Epilogue: fp32 acc fragment -> fp16 fragment in registers, direct global
// store_matrix_sync (no smem staging, no epilogue syncs). Tail block only
// (m0+64 > NN) uses the staged+guarded path.
// ---------------------------------------------------------------------------
__global__ __launch_bounds__(256)
void kqv_gemm_fused(const float* __restrict__ h,
                    const float* __restrict__ wq,
                    const float* __restrict__ wp,
                    const float* __restrict__ wv) {
    extern __shared__ __align__(16) char smem[];
    __half* As = (__half*)smem;             // [64][136]
    __half* Bs = (__half*)(smem + 17408);   // [128][136]
    float*  Cs = (float*)(smem + 17408);    // [64][136] staging (tail only)

    const int m0  = blockIdx.x * 64;
    const int tid = threadIdx.x;
    const bool full_tile = (m0 + 64 <= NN);

    // Load A tile fp32 -> fp16: 64 rows x 32 float4 = 2048, 8/thread
#pragma unroll
    for (int t = 0; t < 8; t++) {
        int i = tid + t * 256;
        int row = i >> 5, c4 = i & 31;
        int gr = m0 + row;
        float4 v = make_float4(0.f, 0.f, 0.f, 0.f);
        if (gr < NN) v = *(const float4*)&h[gr * 128 + c4 * 4];
        __half2 h0 = __floats2half2_rn(v.x, v.y);
        __half2 h1 = __floats2half2_rn(v.z, v.w);
        uint2 pk;
        pk.x = *(unsigned*)&h0;
        pk.y = *(unsigned*)&h1;
        *(uint2*)&As[row * 136 + c4 * 4] = pk;
    }

    const int wid      = tid >> 5;
    const int warp_row = wid >> 2;   // 0..1 (32 rows each)
    const int warp_col = wid & 3;    // 0..3 (32 cols each)

    for (int mat = 0; mat < 3; mat++) {
        __syncthreads();   // prior mat done reading Bs / staging

        // Load B (mat) fp32 -> fp16: 128 rows x 32 float4 = 4096, 16/thread
        const float* w = (mat == 0) ? wq : (mat == 1) ? wp : wv;
#pragma unroll
        for (int t = 0; t < 16; t++) {
            int i = tid + t * 256;
            int row = i >> 5, c4 = i & 31;
            float4 v = *(const float4*)&w[row * 128 + c4 * 4];
            __half2 h0 = __floats2half2_rn(v.x, v.y);
            __half2 h1 = __floats2half2_rn(v.z, v.w);
            uint2 pk;
            pk.x = *(unsigned*)&h0;
            pk.y = *(unsigned*)&h1;
            *(uint2*)&Bs[row * 136 + c4 * 4] = pk;
        }
        __syncthreads();

        wmma::fragment<wmma::accumulator, 16, 16, 16, float> c[2][2];
#pragma unroll
        for (int i = 0; i < 2; i++)
#pragma unroll
            for (int j = 0; j < 2; j++) wmma::fill_fragment(c[i][j], 0.0f);

#pragma unroll
        for (int k = 0; k < 8; k++) {
            wmma::fragment<wmma::matrix_a, 16, 16, 16, __half, wmma::row_major> a[2];
            wmma::fragment<wmma::matrix_b, 16, 16, 16, __half, wmma::row_major> b[2];
#pragma unroll
            for (int i = 0; i < 2; i++)
                wmma::load_matrix_sync(a[i],
                    As + (warp_row * 32 + i * 16) * 136 + k * 16, 136);
#pragma unroll
            for (int j = 0; j < 2; j++)
                wmma::load_matrix_sync(b[j],
                    Bs + (k * 16) * 136 + warp_col * 32 + j * 16, 136);
#pragma unroll
            for (int i = 0; i < 2; i++)
#pragma unroll
                for (int j = 0; j < 2; j++)
                    wmma::mma_sync(c[i][j], a[i], b[j], c[i][j]);
        }

        __half* outp;
        int rstride, coff;
        if (mat == 0)      { outp = g_KV; rstride = 256; coff = 0;   }  // K
        else if (mat == 1) { outp = g_Q;  rstride = 128; coff = 0;   }  // Q
        else               { outp = g_KV; rstride = 256; coff = 128; }  // V

        if (full_tile) {
            // Fast path: convert fragments in registers, store direct to global.
#pragma unroll
            for (int i = 0; i < 2; i++) {
#pragma unroll
                for (int j = 0; j < 2; j++) {
                    wmma::fragment<wmma::accumulator, 16, 16, 16, __half> ch;
#pragma unroll
                    for (int e = 0; e < ch.num_elements; e++)
                        ch.x[e] = __float2half(c[i][j].x[e]);
                    __half* base = outp +
                        (size_t)(m0 + warp_row * 32 + i * 16) * rstride +
                        coff + warp_col * 32 + j * 16;
                    wmma::store_matrix_sync(base, ch, rstride,
                                            wmma::mem_row_major);
                }
            }
            // loop-top __syncthreads() protects Bs for the next mat
        } else {
            // Tail block: stage to smem, guarded scalar stores.
            __syncthreads();   // all warps done reading Bs
#pragma unroll
            for (int i = 0; i < 2; i++)
#pragma unroll
                for (int j = 0; j < 2; j++)
                    wmma::store_matrix_sync(
                        Cs + (warp_row * 32 + i * 16) * 136 +
                            warp_col * 32 + j * 16,
                        c[i][j], 136, wmma::mem_row_major);
            __syncthreads();
#pragma unroll
            for (int t = 0; t < 16; t++) {
                int i = tid + t * 256;          // 0..4095
                int row = i >> 6, cp = i & 63;
                int gr = m0 + row;
                if (gr < NN) {
                    float2 f = *(float2*)&Cs[row * 136 + cp * 2];
                    __half2 hv = __floats2half2_rn(f.x, f.y);
                    *(unsigned*)&outp[(size_t)gr * rstride + coff + cp * 2] =
                        *(unsigned*)&hv;
                }
            }
        }
    }
}

// ---------------------------------------------------------------------------
// Counting sort by dst.
// ---------------------------------------------------------------------------
__global__ void hist_kernel(const int* __restrict__ dst, int E) {
    if (blockIdx.x == 0 && threadIdx.x < 256) g_scanstate[threadIdx.x] = 0ULL;
    int e = blockIdx.x * blockDim.x + threadIdx.x;
    if (e < E) atomicAdd(&g_count[dst[e]], 1);
}

// Single-pass decoupled-lookback exclusive scan; also re-zeroes g_count.
__global__ void scan_fused(int E) {
    __shared__ int sh[256];
    __shared__ int s_prefix;
    const int b = blockIdx.x;
    const int i = b * 256 + threadIdx.x;
    int v = (i < NN) ? g_count[i] : 0;
    sh[threadIdx.x] = v;
    __syncthreads();
#pragma unroll
    for (int off = 1; off < 256; off <<= 1) {
        int t = (threadIdx.x >= off) ? sh[threadIdx.x - off] : 0;
        __syncthreads();
        sh[threadIdx.x] += t;
        __syncthreads();
    }
    const int total = sh[255];

    if (threadIdx.x == 0) {
        unsigned long long st;
        if (b == 0)
            st = (2ULL << 32) | (unsigned)total;   // inclusive known
        else
            st = (1ULL << 32) | (unsigned)total;   // aggregate only
        atomicExch(&g_scanstate[b], st);

        int prefix = 0;
        if (b > 0) {
            int j = b - 1;
            while (true) {
                unsigned long long s = atomicAdd(&g_scanstate[j], 0ULL);
                unsigned flag = (unsigned)(s >> 32);
                if (flag == 2u) { prefix += (int)(unsigned)s; break; }
                if (flag == 1u) { prefix += (int)(unsigned)s; j--; }
            }
            atomicExch(&g_scanstate[b],
                       (2ULL << 32) | (unsigned)(prefix + total));
        }
        s_prefix = prefix;
    }
    __syncthreads();

    if (i < NN) {
        int r = s_prefix + sh[threadIdx.x] - v;   // exclusive
        g_rowstart[i] = r;
        g_cursor[i]   = r;
        g_count[i]    = 0;                        // reset for next call
    }
    if (i == 0) g_rowstart[NN] = E;
}

__global__ void scatter_kernel(const int* __restrict__ src,
                               const int* __restrict__ dst, int E) {
    int e = blockIdx.x * blockDim.x + threadIdx.x;
    if (e < E) {
        int pos = atomicAdd(&g_cursor[dst[e]], 1);
        g_sorted_src[pos] = src[e];
    }
}

// ---------------------------------------------------------------------------
// Node kernel: one warp per dst node, 4-edge unroll (8 gathers in flight).
// K/V interleaved: one 512B row per src node. lane t: head=t>>2, ch [4t,4t+4).
// ---------------------------------------------------------------------------
__global__ __launch_bounds__(64)
void node_kernel(float* __restrict__ out) {
    const int lane = threadIdx.x & 31;
    const int d    = (blockIdx.x * blockDim.x + threadIdx.x) >> 5;
    if (d >= NN) return;

    const uint2* __restrict__ KV2 = (const uint2*)g_KV;   // 64 uint2 per node
    const uint2* __restrict__ Q2  = (const uint2*)g_Q;

    uint2 qr = Q2[d * 32 + lane];
    float2 q0 = __half22float2(*(__half2*)&qr.x);
    float2 q1 = __half22float2(*(__half2*)&qr.y);

    const int beg = g_rowstart[d];
    const int end = g_rowstart[d + 1];

    float a0 = 0.f, a1 = 0.f, a2 = 0.f, a3 = 0.f, z = 0.f;

    int i = beg;
    for (; i + 4 <= end; i += 4) {
        int s0 = g_sorted_src[i];
        int s1 = g_sorted_src[i + 1];
        int s2 = g_sorted_src[i + 2];
        int s3 = g_sorted_src[i + 3];

        uint2 kr0 = KV2[s0 * 64 + lane];
        uint2 vr0 = KV2[s0 * 64 + 32 + lane];
        uint2 kr1 = KV2[s1 * 64 + lane];
        uint2 vr1 = KV2[s1 * 64 + 32 + lane];
        uint2 kr2 = KV2[s2 * 64 + lane];
        uint2 vr2 = KV2[s2 * 64 + 32 + lane];
        uint2 kr3 = KV2[s3 * 64 + lane];
        uint2 vr3 = KV2[s3 * 64 + 32 + lane];

        float2 k00 = __half22float2(*(__half2*)&kr0.x);
        float2 k01 = __half22float2(*(__half2*)&kr0.y);
        float2 k10 = __half22float2(*(__half2*)&kr1.x);
        float2 k11 = __half22float2(*(__half2*)&kr1.y);
        float2 k20 = __half22float2(*(__half2*)&kr2.x);
        float2 k21 = __half22float2(*(__half2*)&kr2.y);
        float2 k30 = __half22float2(*(__half2*)&kr3.x);
        float2 k31 = __half22float2(*(__half2*)&kr3.y);

        float p0 = k00.x * q0.x + k00.y * q0.y + k01.x * q1.x + k01.y * q1.y;
        float p1 = k10.x * q0.x + k10.y * q0.y + k11.x * q1.x + k11.y * q1.y;
        float p2 = k20.x * q0.x + k20.y * q0.y + k21.x * q1.x + k21.y * q1.y;
        float p3 = k30.x * q0.x + k30.y * q0.y + k31.x * q1.x + k31.y * q1.y;
        p0 += __shfl_xor_sync(0xFFFFFFFFu, p0, 1);
        p1 += __shfl_xor_sync(0xFFFFFFFFu, p1, 1);
        p2 += __shfl_xor_sync(0xFFFFFFFFu, p2, 1);
        p3 += __shfl_xor_sync(0xFFFFFFFFu, p3, 1);
        p0 += __shfl_xor_sync(0xFFFFFFFFu, p0, 2);
        p1 += __shfl_xor_sync(0xFFFFFFFFu, p1, 2);
        p2 += __shfl_xor_sync(0xFFFFFFFFu, p2, 2);
        p3 += __shfl_xor_sync(0xFFFFFFFFu, p3, 2);
        float sc0 = __expf(fminf(fmaxf(p0 * 0.25f, -5.f), 5.f));
        float sc1 = __expf(fminf(fmaxf(p1 * 0.25f, -5.f), 5.f));
        float sc2 = __expf(fminf(fmaxf(p2 * 0.25f, -5.f), 5.f));
        float sc3 = __expf(fminf(fmaxf(p3 * 0.25f, -5.f), 5.f));

        float2 v00 = __half22float2(*(__half2*)&vr0.x);
        float2 v01 = __half22float2(*(__half2*)&vr0.y);
        float2 v10 = __half22float2(*(__half2*)&vr1.x);
        float2 v11 = __half22float2(*(__half2*)&vr1.y);
        float2 v20 = __half22float2(*(__half2*)&vr2.x);
        float2 v21 = __half22float2(*(__half2*)&vr2.y);
        float2 v30 = __half22float2(*(__half2*)&vr3.x);
        float2 v31 = __half22float2(*(__half2*)&vr3.y);

        a0 = fmaf(v00.x, sc0, a0); a1 = fmaf(v00.y, sc0, a1);
        a2 = fmaf(v01.x, sc0, a2); a3 = fmaf(v01.y, sc0, a3);
        a0 = fmaf(v10.x, sc1, a0); a1 = fmaf(v10.y, sc1, a1);
        a2 = fmaf(v11.x, sc1, a2); a3 = fmaf(v11.y, sc1, a3);
        a0 = fmaf(v20.x, sc2, a0); a1 = fmaf(v20.y, sc2, a1);
        a2 = fmaf(v21.x, sc2, a2); a3 = fmaf(v21.y, sc2, a3);
        a0 = fmaf(v30.x, sc3, a0); a1 = fmaf(v30.y, sc3, a1);
        a2 = fmaf(v31.x, sc3, a2); a3 = fmaf(v31.y, sc3, a3);
        z += (sc0 + sc1) + (sc2 + sc3);
    }
    for (; i < end; i++) {
        int s = g_sorted_src[i];
        uint2 kr = KV2[s * 64 + lane];
        uint2 vr = KV2[s * 64 + 32 + lane];
        float2 k0 = __half22float2(*(__half2*)&kr.x);
        float2 k1 = __half22float2(*(__half2*)&kr.y);
        float ps = k0.x * q0.x + k0.y * q0.y + k1.x * q1.x + k1.y * q1.y;
        ps += __shfl_xor_sync(0xFFFFFFFFu, ps, 1);
        ps += __shfl_xor_sync(0xFFFFFFFFu, ps, 2);
        float sc = __expf(fminf(fmaxf(ps * 0.25f, -5.f), 5.f));
        float2 v0 = __half22float2(*(__half2*)&vr.x);
        float2 v1 = __half22float2(*(__half2*)&vr.y);
        a0 = fmaf(v0.x, sc, a0); a1 = fmaf(v0.y, sc, a1);
        a2 = fmaf(v1.x, sc, a2); a3 = fmaf(v1.y, sc, a3);
        z += sc;
    }

    float zz = (z == 0.f) ? 0.001f : z;
    float inv = 1.0f / zz;
    float4 r = make_float4(a0 * inv, a1 * inv, a2 * inv, a3 * inv);
    *(float4*)&out[d * 128 + lane * 4] = r;
}

// ---------------------------------------------------------------------------
static cudaStream_t g_s2;
static cudaEvent_t  g_evFork, g_evJoin;
static int          g_streams_ready = 0;

extern "C" void kernel_launch(void* const* d_in, const int* in_sizes, int n_in,
                              void* d_out, int out_size) {
    const float* h   = (const float*)d_in[0];
    const int*   src = (const int*)d_in[1];
    const int*   dst = (const int*)d_in[2];
    const float* p   = (const float*)d_in[3];
    const float* q   = (const float*)d_in[4];
    const float* wv  = (const float*)d_in[5];
    float* out = (float*)d_out;
    const int E = in_sizes[1];
    const int eg = (E + 255) / 256;

    if (!g_streams_ready) {
        cudaStreamCreateWithFlags(&g_s2, cudaStreamNonBlocking);
        cudaEventCreateWithFlags(&g_evFork, cudaEventDisableTiming);
        cudaEventCreateWithFlags(&g_evJoin, cudaEventDisableTiming);
        cudaFuncSetAttribute(kqv_gemm_fused,
                             cudaFuncAttributeMaxDynamicSharedMemorySize,
                             GEMM_SMEM);
        g_streams_ready = 1;
    }

    // Fork: sort chain on g_s2, projection chain on default stream.
    cudaEventRecord(g_evFork, 0);
    cudaStreamWaitEvent(g_s2, g_evFork, 0);

    hist_kernel<<<eg, 256, 0, g_s2>>>(dst, E);
    scan_fused<<<SCAN_BLOCKS, 256, 0, g_s2>>>(E);
    scatter_kernel<<<eg, 256, 0, g_s2>>>(src, dst, E);
    cudaEventRecord(g_evJoin, g_s2);

    kqv_gemm_fused<<<(NN + 63) / 64, 256, GEMM_SMEM>>>(h, q, p, wv);

    // Join, then the consumer of both chains.
    cudaStreamWaitEvent(0, g_evJoin, 0);
    node_kernel<<<(NN * 32 + 63) / 64, 64>>>(out);
}

// round 15
// speedup vs baseline: 1.0576x; 1.0576x over previous
#include <cuda_runtime.h>
#include <cuda_fp16.h>
#include <cuda_bf16.h>
#include <mma.h>
#include <cstdint>

using namespace nvcuda;

#define NN    50000
#define EMAX  1700000
#define HEADS 8

// Scratch (no cudaMalloc allowed)
__device__ __half g_KV[NN * 256];          // per node: 128 K halves | 128 V halves
__device__ __half g_Q[NN * 128];
__device__ int    g_count[NN];             // zero at load; re-zeroed every call
__device__ int    g_rowstart[NN + 1];
__device__ int    g_cursor[NN];
__device__ unsigned long long g_scanstate[256];
__device__ int    g_sorted_src[EMAX];

#define SCAN_BLOCKS 196   // 196*256 = 50176 >= NN
#define GEMM_SMEM   52224 // 17408 (A) + 34816 (B); fp16 C-staging aliases B

// ---------------------------------------------------------------------------
// Fused K/Q/V projection via WMMA. One block: 64 rows x full 128 cols,
// all 3 matrices. 8 warps in 2x4, each a 32x32 tile (2x2 fragments).
// Epilogue: acc -> fp16 fragment in registers, staged in smem (fp16, half the
// bytes of fp32 staging), then coalesced uint4 global stores.
// ---------------------------------------------------------------------------
__global__ __launch_bounds__(256)
void kqv_gemm_fused(const float* __restrict__ h,
                    const float* __restrict__ wq,
                    const float* __restrict__ wp,
                    const float* __restrict__ wv) {
    extern __shared__ __align__(16) char smem[];
    __half* As  = (__half*)smem;             // [64][136]
    __half* Bs  = (__half*)(smem + 17408);   // [128][136]
    __half* Chs = (__half*)(smem + 17408);   // [64][136] fp16 staging (aliases Bs)

    const int m0  = blockIdx.x * 64;
    const int tid = threadIdx.x;

    // Load A tile fp32 -> fp16: 64 rows x 32 float4 = 2048, 8/thread
#pragma unroll
    for (int t = 0; t < 8; t++) {
        int i = tid + t * 256;
        int row = i >> 5, c4 = i & 31;
        int gr = m0 + row;
        float4 v = make_float4(0.f, 0.f, 0.f, 0.f);
        if (gr < NN) v = *(const float4*)&h[gr * 128 + c4 * 4];
        __half2 h0 = __floats2half2_rn(v.x, v.y);
        __half2 h1 = __floats2half2_rn(v.z, v.w);
        uint2 pk;
        pk.x = *(unsigned*)&h0;
        pk.y = *(unsigned*)&h1;
        *(uint2*)&As[row * 136 + c4 * 4] = pk;
    }

    const int wid      = tid >> 5;
    const int warp_row = wid >> 2;   // 0..1 (32 rows each)
    const int warp_col = wid & 3;    // 0..3 (32 cols each)

    for (int mat = 0; mat < 3; mat++) {
        __syncthreads();   // prior mat done reading staging (=Bs region)

        // Load B (mat) fp32 -> fp16: 128 rows x 32 float4 = 4096, 16/thread
        const float* w = (mat == 0) ? wq : (mat == 1) ? wp : wv;
#pragma unroll
        for (int t = 0; t < 16; t++) {
            int i = tid + t * 256;
            int row = i >> 5, c4 = i & 31;
            float4 v = *(const float4*)&w[row * 128 + c4 * 4];
            __half2 h0 = __floats2half2_rn(v.x, v.y);
            __half2 h1 = __floats2half2_rn(v.z, v.w);
            uint2 pk;
            pk.x = *(unsigned*)&h0;
            pk.y = *(unsigned*)&h1;
            *(uint2*)&Bs[row * 136 + c4 * 4] = pk;
        }
        __syncthreads();

        wmma::fragment<wmma::accumulator, 16, 16, 16, float> c[2][2];
#pragma unroll
        for (int i = 0; i < 2; i++)
#pragma unroll
            for (int j = 0; j < 2; j++) wmma::fill_fragment(c[i][j], 0.0f);

#pragma unroll
        for (int k = 0; k < 8; k++) {
            wmma::fragment<wmma::matrix_a, 16, 16, 16, __half, wmma::row_major> a[2];
            wmma::fragment<wmma::matrix_b, 16, 16, 16, __half, wmma::row_major> b[2];
#pragma unroll
            for (int i = 0; i < 2; i++)
                wmma::load_matrix_sync(a[i],
                    As + (warp_row * 32 + i * 16) * 136 + k * 16, 136);
#pragma unroll
            for (int j = 0; j < 2; j++)
                wmma::load_matrix_sync(b[j],
                    Bs + (k * 16) * 136 + warp_col * 32 + j * 16, 136);
#pragma unroll
            for (int i = 0; i < 2; i++)
#pragma unroll
                for (int j = 0; j < 2; j++)
                    wmma::mma_sync(c[i][j], a[i], b[j], c[i][j]);
        }
        __syncthreads();   // all warps done reading Bs before staging overwrite

        // Convert acc -> fp16 fragments in registers; stage fp16 in smem.
#pragma unroll
        for (int i = 0; i < 2; i++) {
#pragma unroll
            for (int j = 0; j < 2; j++) {
                wmma::fragment<wmma::accumulator, 16, 16, 16, __half> ch;
#pragma unroll
                for (int e = 0; e < ch.num_elements; e++)
                    ch.x[e] = __float2half(c[i][j].x[e]);
                wmma::store_matrix_sync(
                    Chs + (warp_row * 32 + i * 16) * 136 + warp_col * 32 + j * 16,
                    ch, 136, wmma::mem_row_major);
            }
        }
        __syncthreads();

        // Coalesced uint4 copy to global. K/V interleave in g_KV.
        __half* outp;
        int rstride, coff;
        if (mat == 0)      { outp = g_KV; rstride = 256; coff = 0;   }  // K
        else if (mat == 1) { outp = g_Q;  rstride = 128; coff = 0;   }  // Q
        else               { outp = g_KV; rstride = 256; coff = 128; }  // V
#pragma unroll
        for (int t = 0; t < 4; t++) {
            int i = tid + t * 256;          // 0..1023: 64 rows x 16 uint4
            int row = i >> 4, c8 = i & 15;
            int gr = m0 + row;
            if (gr < NN) {
                *(uint4*)&outp[(size_t)gr * rstride + coff + c8 * 8] =
                    *(uint4*)&Chs[row * 136 + c8 * 8];
            }
        }
    }
}

// ---------------------------------------------------------------------------
// Counting sort by dst.
// ---------------------------------------------------------------------------
__global__ void hist_kernel(const int* __restrict__ dst, int E) {
    if (blockIdx.x == 0 && threadIdx.x < 256) g_scanstate[threadIdx.x] = 0ULL;
    int e = blockIdx.x * blockDim.x + threadIdx.x;
    if (e < E) atomicAdd(&g_count[dst[e]], 1);
}

// Single-pass decoupled-lookback exclusive scan; also re-zeroes g_count.
__global__ void scan_fused(int E) {
    __shared__ int sh[256];
    __shared__ int s_prefix;
    const int b = blockIdx.x;
    const int i = b * 256 + threadIdx.x;
    int v = (i < NN) ? g_count[i] : 0;
    sh[threadIdx.x] = v;
    __syncthreads();
#pragma unroll
    for (int off = 1; off < 256; off <<= 1) {
        int t = (threadIdx.x >= off) ? sh[threadIdx.x - off] : 0;
        __syncthreads();
        sh[threadIdx.x] += t;
        __syncthreads();
    }
    const int total = sh[255];

    if (threadIdx.x == 0) {
        unsigned long long st;
        if (b == 0)
            st = (2ULL << 32) | (unsigned)total;   // inclusive known
        else
            st = (1ULL << 32) | (unsigned)total;   // aggregate only
        atomicExch(&g_scanstate[b], st);

        int prefix = 0;
        if (b > 0) {
            int j = b - 1;
            while (true) {
                unsigned long long s = atomicAdd(&g_scanstate[j], 0ULL);
                unsigned flag = (unsigned)(s >> 32);
                if (flag == 2u) { prefix += (int)(unsigned)s; break; }
                if (flag == 1u) { prefix += (int)(unsigned)s; j--; }
            }
            atomicExch(&g_scanstate[b],
                       (2ULL << 32) | (unsigned)(prefix + total));
        }
        s_prefix = prefix;
    }
    __syncthreads();

    if (i < NN) {
        int r = s_prefix + sh[threadIdx.x] - v;   // exclusive
        g_rowstart[i] = r;
        g_cursor[i]   = r;
        g_count[i]    = 0;                        // reset for next call
    }
    if (i == 0) g_rowstart[NN] = E;
}

__global__ void scatter_kernel(const int* __restrict__ src,
                               const int* __restrict__ dst, int E) {
    int e = blockIdx.x * blockDim.x + threadIdx.x;
    if (e < E) {
        int pos = atomicAdd(&g_cursor[dst[e]], 1);
        g_sorted_src[pos] = src[e];
    }
}

// ---------------------------------------------------------------------------
// Node kernel: one warp per dst node, 2-edge unroll (4 gathers in flight).
// K/V interleaved: one 512B row per src node. lane t: head=t>>2, ch [4t,4t+4).
// ---------------------------------------------------------------------------
__global__ __launch_bounds__(64)
void node_kernel(float* __restrict__ out) {
    const int lane = threadIdx.x & 31;
    const int d    = (blockIdx.x * blockDim.x + threadIdx.x) >> 5;
    if (d >= NN) return;

    const uint2* __restrict__ KV2 = (const uint2*)g_KV;   // 64 uint2 per node
    const uint2* __restrict__ Q2  = (const uint2*)g_Q;

    uint2 qr = Q2[d * 32 + lane];
    float2 q0 = __half22float2(*(__half2*)&qr.x);
    float2 q1 = __half22float2(*(__half2*)&qr.y);

    const int beg = g_rowstart[d];
    const int end = g_rowstart[d + 1];

    float a0 = 0.f, a1 = 0.f, a2 = 0.f, a3 = 0.f, z = 0.f;

    int i = beg;
    for (; i + 2 <= end; i += 2) {
        int s0 = g_sorted_src[i];
        int s1 = g_sorted_src[i + 1];

        uint2 kr0 = KV2[s0 * 64 + lane];
        uint2 vr0 = KV2[s0 * 64 + 32 + lane];
        uint2 kr1 = KV2[s1 * 64 + lane];
        uint2 vr1 = KV2[s1 * 64 + 32 + lane];

        float2 k00 = __half22float2(*(__half2*)&kr0.x);
        float2 k01 = __half22float2(*(__half2*)&kr0.y);
        float2 k10 = __half22float2(*(__half2*)&kr1.x);
        float2 k11 = __half22float2(*(__half2*)&kr1.y);

        float p0 = k00.x * q0.x + k00.y * q0.y + k01.x * q1.x + k01.y * q1.y;
        float p1 = k10.x * q0.x + k10.y * q0.y + k11.x * q1.x + k11.y * q1.y;
        p0 += __shfl_xor_sync(0xFFFFFFFFu, p0, 1);
        p1 += __shfl_xor_sync(0xFFFFFFFFu, p1, 1);
        p0 += __shfl_xor_sync(0xFFFFFFFFu, p0, 2);
        p1 += __shfl_xor_sync(0xFFFFFFFFu, p1, 2);
        float sc0 = __expf(fminf(fmaxf(p0 * 0.25f, -5.f), 5.f));
        float sc1 = __expf(fminf(fmaxf(p1 * 0.25f, -5.f), 5.f));

        float2 v00 = __half22float2(*(__half2*)&vr0.x);
        float2 v01 = __half22float2(*(__half2*)&vr0.y);
        float2 v10 = __half22float2(*(__half2*)&vr1.x);
        float2 v11 = __half22float2(*(__half2*)&vr1.y);

        a0 = fmaf(v00.x, sc0, a0); a1 = fmaf(v00.y, sc0, a1);
        a2 = fmaf(v01.x, sc0, a2); a3 = fmaf(v01.y, sc0, a3);
        a0 = fmaf(v10.x, sc1, a0); a1 = fmaf(v10.y, sc1, a1);
        a2 = fmaf(v11.x, sc1, a2); a3 = fmaf(v11.y, sc1, a3);
        z += sc0 + sc1;
    }
    if (i < end) {
        int s = g_sorted_src[i];
        uint2 kr = KV2[s * 64 + lane];
        uint2 vr = KV2[s * 64 + 32 + lane];
        float2 k0 = __half22float2(*(__half2*)&kr.x);
        float2 k1 = __half22float2(*(__half2*)&kr.y);
        float ps = k0.x * q0.x + k0.y * q0.y + k1.x * q1.x + k1.y * q1.y;
        ps += __shfl_xor_sync(0xFFFFFFFFu, ps, 1);
        ps += __shfl_xor_sync(0xFFFFFFFFu, ps, 2);
        float sc = __expf(fminf(fmaxf(ps * 0.25f, -5.f), 5.f));
        float2 v0 = __half22float2(*(__half2*)&vr.x);
        float2 v1 = __half22float2(*(__half2*)&vr.y);
        a0 = fmaf(v0.x, sc, a0); a1 = fmaf(v0.y, sc, a1);
        a2 = fmaf(v1.x, sc, a2); a3 = fmaf(v1.y, sc, a3);
        z += sc;
    }

    float zz = (z == 0.f) ? 0.001f : z;
    float inv = 1.0f / zz;
    float4 r = make_float4(a0 * inv, a1 * inv, a2 * inv, a3 * inv);
    *(float4*)&out[d * 128 + lane * 4] = r;
}

// ---------------------------------------------------------------------------
static cudaStream_t g_s2;
static cudaEvent_t  g_evFork, g_evJoin;
static int          g_streams_ready = 0;

extern "C" void kernel_launch(void* const* d_in, const int* in_sizes, int n_in,
                              void* d_out, int out_size) {
    const float* h   = (const float*)d_in[0];
    const int*   src = (const int*)d_in[1];
    const int*   dst = (const int*)d_in[2];
    const float* p   = (const float*)d_in[3];
    const float* q   = (const float*)d_in[4];
    const float* wv  = (const float*)d_in[5];
    float* out = (float*)d_out;
    const int E = in_sizes[1];
    const int eg = (E + 255) / 256;

    if (!g_streams_ready) {
        cudaStreamCreateWithFlags(&g_s2, cudaStreamNonBlocking);
        cudaEventCreateWithFlags(&g_evFork, cudaEventDisableTiming);
        cudaEventCreateWithFlags(&g_evJoin, cudaEventDisableTiming);
        cudaFuncSetAttribute(kqv_gemm_fused,
                             cudaFuncAttributeMaxDynamicSharedMemorySize,
                             GEMM_SMEM);
        g_streams_ready = 1;
    }

    // Fork: sort chain on g_s2, projection chain on default stream.
    cudaEventRecord(g_evFork, 0);
    cudaStreamWaitEvent(g_s2, g_evFork, 0);

    hist_kernel<<<eg, 256, 0, g_s2>>>(dst, E);
    scan_fused<<<SCAN_BLOCKS, 256, 0, g_s2>>>(E);
    scatter_kernel<<<eg, 256, 0, g_s2>>>(src, dst, E);
    cudaEventRecord(g_evJoin, g_s2);

    kqv_gemm_fused<<<(NN + 63) / 64, 256, GEMM_SMEM>>>(h, q, p, wv);

    // Join, then the consumer of both chains.
    cudaStreamWaitEvent(0, g_evJoin, 0);
    node_kernel<<<(NN * 32 + 63) / 64, 64>>>(out);
}